// round 9
// baseline (speedup 1.0000x reference)
#include <cuda_runtime.h>
#include <math.h>

// Problem constants: B=32, T=384, D=512, H=16, d=32, chunks of 128.

// Scratch (device globals; allocation-free per harness rules)
__device__ float g_q [6291456];   // (chunks, B, Tb, 512) linear proj
__device__ float g_k [6291456];
__device__ float g_v [6291456];
__device__ float g_xr[6291456];   // x_ = blk0 output, residual
__device__ float g_t1[6291456];   // tmp_layer1
__device__ float g_t2[6291456];   // tmp_layer2
__device__ float g_ln[6291456];   // layernorm(tmp_layer1)
__device__ float g_S [75497472];  // attention matrices (up to 512 * 384*384)

// ---------------------------------------------------------------------------
// GEMM: out[c, r, j] = sum_k A[b, c*Tb + t, k] * W_c[j, k] (+ bias_c[j])
//   A = X (or X - X2 if X2 != nullptr, fused elementwise diff).
//   X is (B, 384, 512) row-major. r = b*Tb + t (chunk-local row).
//   W_c = W + c*wStride (row-major (512,512)), bias_c = bias + c*bStride.
//   128x64 tile, k-step 16, 256 threads, 8x4 per thread.
//   Software-pipelined: next k-step's global loads prefetched into registers.
// ---------------------------------------------------------------------------
__global__ __launch_bounds__(256) void gemm512(
    const float* __restrict__ X, const float* __restrict__ X2,
    const float* __restrict__ W,
    const float* __restrict__ bias, float* __restrict__ out,
    int Tb, int wStride, int bStride)
{
    int c = blockIdx.z;
    const float* Wc = W + (size_t)c * wStride;
    int N = 32 * Tb;
    int row0 = blockIdx.y * 128;
    int col0 = blockIdx.x * 64;
    int tid = threadIdx.x;
    int tx = tid & 15, ty = tid >> 4;      // tx: col group, ty: row group

    __shared__ float As[16][128];   // [k][row]
    __shared__ float Bs[16][64];    // [k][col]

    float acc[8][4];
#pragma unroll
    for (int i = 0; i < 8; i++)
#pragma unroll
        for (int j = 0; j < 4; j++) acc[i][j] = 0.0f;

    // ---- A-tile loading: 128 rows x 16 k = 512 float4; 2 per thread ----
    int a_r  = tid & 127;                  // row within tile
    int a_kq = tid >> 7;                   // 0..1 -> k-quads {a_kq, a_kq+2}
    int grow = row0 + a_r;
    int b_ = grow / Tb;
    int t_ = grow - b_ * Tb;
    size_t xoff = ((size_t)b_ * 384 + (size_t)c * Tb + t_) * 512;
    const float* xrow  = X + xoff;
    const float* x2row = X2 ? (X2 + xoff) : nullptr;

    // ---- B-tile loading: 64 rows x 16 k = 256 float4; 1 per thread ----
    int w_r  = tid & 63;
    int w_kq = tid >> 6;                   // 0..3
    const float* wrow = Wc + (size_t)(col0 + w_r) * 512;

    // Prologue: first k-step fragments
    float4 xa0 = *(const float4*)(xrow + a_kq * 4);
    float4 xa1 = *(const float4*)(xrow + (a_kq + 2) * 4);
    if (x2row) {
        float4 d0 = *(const float4*)(x2row + a_kq * 4);
        float4 d1 = *(const float4*)(x2row + (a_kq + 2) * 4);
        xa0.x -= d0.x; xa0.y -= d0.y; xa0.z -= d0.z; xa0.w -= d0.w;
        xa1.x -= d1.x; xa1.y -= d1.y; xa1.z -= d1.z; xa1.w -= d1.w;
    }
    float4 wa = *(const float4*)(wrow + w_kq * 4);

    for (int k0 = 0; k0 < 512; k0 += 16) {
        int ak0 = a_kq * 4, ak1 = (a_kq + 2) * 4, wk = w_kq * 4;
        As[ak0 + 0][a_r] = xa0.x; As[ak0 + 1][a_r] = xa0.y;
        As[ak0 + 2][a_r] = xa0.z; As[ak0 + 3][a_r] = xa0.w;
        As[ak1 + 0][a_r] = xa1.x; As[ak1 + 1][a_r] = xa1.y;
        As[ak1 + 2][a_r] = xa1.z; As[ak1 + 3][a_r] = xa1.w;
        Bs[wk + 0][w_r] = wa.x; Bs[wk + 1][w_r] = wa.y;
        Bs[wk + 2][w_r] = wa.z; Bs[wk + 3][w_r] = wa.w;
        __syncthreads();

        // Prefetch next k-step while computing this one
        if (k0 + 16 < 512) {
            int kn = k0 + 16;
            xa0 = *(const float4*)(xrow + kn + a_kq * 4);
            xa1 = *(const float4*)(xrow + kn + (a_kq + 2) * 4);
            if (x2row) {
                float4 d0 = *(const float4*)(x2row + kn + a_kq * 4);
                float4 d1 = *(const float4*)(x2row + kn + (a_kq + 2) * 4);
                xa0.x -= d0.x; xa0.y -= d0.y; xa0.z -= d0.z; xa0.w -= d0.w;
                xa1.x -= d1.x; xa1.y -= d1.y; xa1.z -= d1.z; xa1.w -= d1.w;
            }
            wa = *(const float4*)(wrow + kn + w_kq * 4);
        }

#pragma unroll
        for (int kk = 0; kk < 16; kk++) {
            float4 a0 = *(const float4*)&As[kk][ty * 8];
            float4 a1 = *(const float4*)&As[kk][ty * 8 + 4];
            float4 b4 = *(const float4*)&Bs[kk][tx * 4];
            float a[8] = {a0.x, a0.y, a0.z, a0.w, a1.x, a1.y, a1.z, a1.w};
            float b[4] = {b4.x, b4.y, b4.z, b4.w};
#pragma unroll
            for (int i = 0; i < 8; i++)
#pragma unroll
                for (int j = 0; j < 4; j++) acc[i][j] += a[i] * b[j];
        }
        __syncthreads();
    }

    float4 badd = make_float4(0.f, 0.f, 0.f, 0.f);
    if (bias) {
        const float* bb = bias + (size_t)c * bStride + col0 + tx * 4;
        badd = make_float4(bb[0], bb[1], bb[2], bb[3]);
    }
#pragma unroll
    for (int i = 0; i < 8; i++) {
        int r = row0 + ty * 8 + i;
        float4 o = make_float4(acc[i][0] + badd.x, acc[i][1] + badd.y,
                               acc[i][2] + badd.z, acc[i][3] + badd.w);
        *(float4*)(out + ((size_t)c * N + r) * 512 + col0 + tx * 4) = o;
    }
}

// ---------------------------------------------------------------------------
// Fused scores + softmax:
//   S[g, t, s] = softmax_s( temp * sum_dc K[dc,t] * V[dc,s] )
//   g = c*512 + b*16 + h.  K/V matrices are (32, Tb), row stride Tb, at
//   buf + (c*32+b)*Tb*512 + h*32*Tb  (torch-view reshape).
//   Block: Tb threads (one per s column), owns 32 t-rows (blockIdx.y).
//   S written exactly once, already normalized.
// ---------------------------------------------------------------------------
__global__ void attn_scores_softmax(
    const float* __restrict__ Kb, const float* __restrict__ Vb,
    float* __restrict__ S, const float* __restrict__ temp,
    int Tb, int tempBase)
{
    int g = blockIdx.z;
    int c = g >> 9;               // /512 (B*H)
    int bh = g & 511;
    int b = bh >> 4, h = bh & 15;
    size_t base = (size_t)(c * 32 + b) * Tb * 512 + (size_t)h * 32 * Tb;
    const float* K = Kb + base;
    const float* V = Vb + base;
    float tscale = temp[tempBase + c * 16 + h];

    int t0 = blockIdx.y * 32;
    int tid = threadIdx.x;           // == s
    int lane = tid & 31, wid = tid >> 5;
    int nw = blockDim.x >> 5;        // 12 (full) or 4 (chunk)

    __shared__ float Ks[32][33];     // [dc][t-local]
    __shared__ float red[32][13];    // per-row cross-warp partials
    __shared__ float rowred[32];     // per-row final max / sum

    for (int i = tid; i < 1024; i += blockDim.x) {
        int dc = i >> 5, tl = i & 31;
        Ks[dc][tl] = K[dc * Tb + t0 + tl];
    }
    __syncthreads();

    // acc[r] = temp * sum_dc K[dc, t0+r] * V[dc, s]
    float acc[32];
#pragma unroll
    for (int r = 0; r < 32; r++) acc[r] = 0.0f;
#pragma unroll 4
    for (int dc = 0; dc < 32; dc++) {
        float vv = V[dc * Tb + tid];
#pragma unroll
        for (int r = 0; r < 32; r++) acc[r] += Ks[dc][r] * vv;
    }
#pragma unroll
    for (int r = 0; r < 32; r++) acc[r] *= tscale;

    // ---- row max over s ----
#pragma unroll
    for (int r = 0; r < 32; r++) {
        float m = acc[r];
#pragma unroll
        for (int o = 16; o > 0; o >>= 1)
            m = fmaxf(m, __shfl_xor_sync(0xffffffffu, m, o));
        if (lane == 0) red[r][wid] = m;
    }
    __syncthreads();
    if (tid < 32) {
        float m = red[tid][0];
        for (int w = 1; w < nw; w++) m = fmaxf(m, red[tid][w]);
        rowred[tid] = m;
    }
    __syncthreads();

    // ---- exp + row sum ----
    float rowmax[32];
#pragma unroll
    for (int r = 0; r < 32; r++) rowmax[r] = rowred[r];
    __syncthreads();
#pragma unroll
    for (int r = 0; r < 32; r++) {
        float e = __expf(acc[r] - rowmax[r]);
        acc[r] = e;
        float sm = e;
#pragma unroll
        for (int o = 16; o > 0; o >>= 1)
            sm += __shfl_xor_sync(0xffffffffu, sm, o);
        if (lane == 0) red[r][wid] = sm;
    }
    __syncthreads();
    if (tid < 32) {
        float sm = red[tid][0];
        for (int w = 1; w < nw; w++) sm += red[tid][w];
        rowred[tid] = 1.0f / sm;
    }
    __syncthreads();

    // ---- normalized write (coalesced along s) ----
    float* Sg = S + (size_t)g * Tb * Tb + (size_t)t0 * Tb + tid;
#pragma unroll
    for (int r = 0; r < 32; r++)
        Sg[(size_t)r * Tb] = acc[r] * rowred[r];
}

// ---------------------------------------------------------------------------
// Apply: O[dc, s] = sum_t Q[dc,t] * A[t,s], written to (B,384,512) layout at
//   idx = b*196608 + c*Tb*512 + h*32*Tb + dc*Tb + s  (+ optional residual)
// ---------------------------------------------------------------------------
__global__ __launch_bounds__(256) void attn_out(
    const float* __restrict__ Qb, const float* __restrict__ S,
    const float* __restrict__ resid, float* __restrict__ out, int Tb)
{
    int g = blockIdx.z;
    int c = g >> 9;
    int bh = g & 511;
    int b = bh >> 4, h = bh & 15;
    const float* Q = Qb + (size_t)(c * 32 + b) * Tb * 512 + (size_t)h * 32 * Tb;
    const float* A = S + (size_t)g * Tb * Tb;
    int s0 = blockIdx.x * 32;
    int tid = threadIdx.x;
    int lane = tid & 31;

    __shared__ float Qs[32][33], As[32][33];
    float acc[4] = {0, 0, 0, 0};

    for (int t0 = 0; t0 < Tb; t0 += 32) {
        __syncthreads();
        for (int i = tid; i < 1024; i += 256) {
            int rr = i >> 5, jj = i & 31;
            Qs[rr][jj] = Q[rr * Tb + t0 + jj];                    // [dc][t]
            As[rr][jj] = A[(size_t)(t0 + rr) * Tb + s0 + jj];     // [t][s]
        }
        __syncthreads();
#pragma unroll
        for (int tt = 0; tt < 32; tt++) {
            float av = As[tt][lane];
#pragma unroll
            for (int r = 0; r < 4; r++) {
                int dc = (tid + r * 256) >> 5;
                acc[r] += Qs[dc][tt] * av;
            }
        }
    }

    size_t base = (size_t)b * 196608 + (size_t)c * Tb * 512 + (size_t)h * 32 * Tb;
#pragma unroll
    for (int r = 0; r < 4; r++) {
        int dc = (tid + r * 256) >> 5;
        size_t idx = base + (size_t)dc * Tb + s0 + lane;
        float v = acc[r];
        if (resid) v += resid[idx];
        out[idx] = v;
    }
}

// ---------------------------------------------------------------------------
// LayerNorm over last dim (512), one block (128 threads x float4) per row
// ---------------------------------------------------------------------------
__global__ __launch_bounds__(128) void layernorm_rows(
    const float* __restrict__ X, float* __restrict__ Y,
    const float* __restrict__ gam, const float* __restrict__ bet)
{
    size_t r = blockIdx.x;
    int tid = threadIdx.x;
    float4 v = ((const float4*)(X + r * 512))[tid];
    __shared__ float red[128];

    red[tid] = v.x + v.y + v.z + v.w; __syncthreads();
    for (int o = 64; o > 0; o >>= 1) {
        if (tid < o) red[tid] += red[tid + o];
        __syncthreads();
    }
    float mu = red[0] * (1.0f / 512.0f); __syncthreads();

    float4 d = make_float4(v.x - mu, v.y - mu, v.z - mu, v.w - mu);
    red[tid] = d.x * d.x + d.y * d.y + d.z * d.z + d.w * d.w; __syncthreads();
    for (int o = 64; o > 0; o >>= 1) {
        if (tid < o) red[tid] += red[tid + o];
        __syncthreads();
    }
    float inv = rsqrtf(red[0] * (1.0f / 512.0f) + 1e-5f);

    int cidx = tid * 4;
    float4 o;
    o.x = d.x * inv * gam[cidx + 0] + bet[cidx + 0];
    o.y = d.y * inv * gam[cidx + 1] + bet[cidx + 1];
    o.z = d.z * inv * gam[cidx + 2] + bet[cidx + 2];
    o.w = d.w * inv * gam[cidx + 3] + bet[cidx + 3];
    ((float4*)(Y + r * 512))[tid] = o;
}

// out = t2 + (t1 - t2) * sigmoid(g)   [== softmax fusion gate, bias cancels]
__global__ __launch_bounds__(256) void fuse_out(
    const float* __restrict__ t1, const float* __restrict__ t2,
    const float* __restrict__ gg, float* __restrict__ out, int n4)
{
    int i = blockIdx.x * 256 + threadIdx.x;
    if (i >= n4) return;
    float4 a = ((const float4*)t1)[i];
    float4 b = ((const float4*)t2)[i];
    float4 g = ((const float4*)gg)[i];
    float4 o;
    o.x = b.x + (a.x - b.x) * (1.0f / (1.0f + __expf(-g.x)));
    o.y = b.y + (a.y - b.y) * (1.0f / (1.0f + __expf(-g.y)));
    o.z = b.z + (a.z - b.z) * (1.0f / (1.0f + __expf(-g.z)));
    o.w = b.w + (a.w - b.w) * (1.0f / (1.0f + __expf(-g.w)));
    ((float4*)out)[i] = o;
}

// ---------------------------------------------------------------------------
extern "C" void kernel_launch(void* const* d_in, const int* in_sizes, int n_in,
                              void* d_out, int out_size)
{
    const float* x     = (const float*)d_in[0];
    const float* qw    = (const float*)d_in[1];
    const float* qb    = (const float*)d_in[2];
    const float* kw    = (const float*)d_in[3];
    const float* kb    = (const float*)d_in[4];
    const float* vw    = (const float*)d_in[5];
    const float* vb    = (const float*)d_in[6];
    const float* temp  = (const float*)d_in[7];
    const float* ln_g  = (const float*)d_in[8];
    const float* ln_b  = (const float*)d_in[9];
    const float* fus_w = (const float*)d_in[10];
    const float* fus_b = (const float*)d_in[11];
    (void)fus_b; (void)in_sizes; (void)n_in; (void)out_size;
    float* out = (float*)d_out;

    float *bq, *bk, *bv, *bxr, *bt1, *bt2, *bln, *bS;
    cudaGetSymbolAddress((void**)&bq,  g_q);
    cudaGetSymbolAddress((void**)&bk,  g_k);
    cudaGetSymbolAddress((void**)&bv,  g_v);
    cudaGetSymbolAddress((void**)&bxr, g_xr);
    cudaGetSymbolAddress((void**)&bt1, g_t1);
    cudaGetSymbolAddress((void**)&bt2, g_t2);
    cudaGetSymbolAddress((void**)&bln, g_ln);
    cudaGetSymbolAddress((void**)&bS,  g_S);

    const int WS = 512 * 512;  // per-block weight stride
    const int BS = 512;        // per-block bias stride
    const int n4 = 6291456 / 4;

    // ---- Block 0 (full T=384) -> x_ ----
    dim3 gF(8, 96, 1);         // 64-col x 128-row tiles over 12288 rows
    gemm512<<<gF, 256>>>(x, nullptr, qw + 0 * WS, qb + 0 * BS, bq, 384, WS, BS);
    gemm512<<<gF, 256>>>(x, nullptr, kw + 0 * WS, kb + 0 * BS, bk, 384, WS, BS);
    gemm512<<<gF, 256>>>(x, nullptr, vw + 0 * WS, vb + 0 * BS, bv, 384, WS, BS);
    attn_scores_softmax<<<dim3(1, 12, 512), 384>>>(bk, bv, bS, temp, 384, 0);
    attn_out<<<dim3(12, 1, 512), 256>>>(bq, bS, nullptr, bxr, 384);

    // ---- Chunk blocks 1..3 (T=128 each), batched via gridDim.z -> tmp1 ----
    dim3 gC(8, 32, 3);         // 4096 rows per chunk-block
    gemm512<<<gC, 256>>>(x, nullptr, qw + 1 * WS, qb + 1 * BS, bq, 128, WS, BS);
    gemm512<<<gC, 256>>>(x, nullptr, kw + 1 * WS, kb + 1 * BS, bk, 128, WS, BS);
    gemm512<<<gC, 256>>>(x, nullptr, vw + 1 * WS, vb + 1 * BS, bv, 128, WS, BS);
    attn_scores_softmax<<<dim3(1, 4, 1536), 128>>>(bk, bv, bS, temp, 128, 16);
    attn_out<<<dim3(4, 1, 1536), 256>>>(bq, bS, bxr, bt1, 128);

    // ---- LayerNorm(tmp1) ----
    layernorm_rows<<<12288, 128>>>(bt1, bln, ln_g, ln_b);

    // ---- Block 4 (full T=384) on ln -> tmp2 ----
    gemm512<<<gF, 256>>>(bln, nullptr, qw + 4 * WS, qb + 4 * BS, bq, 384, WS, BS);
    gemm512<<<gF, 256>>>(bln, nullptr, kw + 4 * WS, kb + 4 * BS, bk, 384, WS, BS);
    gemm512<<<gF, 256>>>(bln, nullptr, vw + 4 * WS, vb + 4 * BS, bv, 384, WS, BS);
    attn_scores_softmax<<<dim3(1, 12, 512), 384>>>(bk, bv, bS, temp, 384, 64);
    attn_out<<<dim3(12, 1, 512), 256>>>(bq, bS, bxr, bt2, 384);

    // ---- Fusion gate: g = (tmp1 - tmp2) @ fus_w^T (bias cancels in softmax;
    //      diff fused into the GEMM's A-tile load) ----
    gemm512<<<gF, 256>>>(bt1, bt2, fus_w, nullptr, bk, 384, 0, 0);
    fuse_out<<<(n4 + 255) / 256, 256>>>(bt1, bt2, bk, out, n4);
}

// round 16
// speedup vs baseline: 1.3322x; 1.3322x over previous
#include <cuda_runtime.h>
#include <math.h>

// Problem constants: B=32, T=384, D=512, H=16, d=32, chunks of 128.

// Scratch (device globals; allocation-free per harness rules)
__device__ float g_q [6291456];   // (chunks, B, Tb, 512) linear proj
__device__ float g_k [6291456];
__device__ float g_v [6291456];
__device__ float g_xr[6291456];   // x_ = blk0 output, residual
__device__ float g_t1[6291456];   // tmp_layer1
__device__ float g_t2[6291456];   // tmp_layer2
__device__ float g_ln[6291456];   // layernorm(tmp_layer1)
__device__ float g_S [75497472];  // attention matrices (up to 512 * 384*384)

// ---------------------------------------------------------------------------
// GEMM: out[c, r, j] = sum_k A[b, c*Tb + t, k] * W_c[j, k] (+ bias_c[j])
//   A = X (or X - X2 if X2 != nullptr, fused elementwise diff).
//   128x64 tile, k-step 16, 256 threads, 8x4 per thread, SW-pipelined.
// ---------------------------------------------------------------------------
__global__ __launch_bounds__(256) void gemm512(
    const float* __restrict__ X, const float* __restrict__ X2,
    const float* __restrict__ W,
    const float* __restrict__ bias, float* __restrict__ out,
    int Tb, int wStride, int bStride)
{
    int c = blockIdx.z;
    const float* Wc = W + (size_t)c * wStride;
    int N = 32 * Tb;
    int row0 = blockIdx.y * 128;
    int col0 = blockIdx.x * 64;
    int tid = threadIdx.x;
    int tx = tid & 15, ty = tid >> 4;      // tx: col group, ty: row group

    __shared__ float As[16][128];   // [k][row]
    __shared__ float Bs[16][64];    // [k][col]

    float acc[8][4];
#pragma unroll
    for (int i = 0; i < 8; i++)
#pragma unroll
        for (int j = 0; j < 4; j++) acc[i][j] = 0.0f;

    int a_r  = tid & 127;
    int a_kq = tid >> 7;
    int grow = row0 + a_r;
    int b_ = grow / Tb;
    int t_ = grow - b_ * Tb;
    size_t xoff = ((size_t)b_ * 384 + (size_t)c * Tb + t_) * 512;
    const float* xrow  = X + xoff;
    const float* x2row = X2 ? (X2 + xoff) : nullptr;

    int w_r  = tid & 63;
    int w_kq = tid >> 6;
    const float* wrow = Wc + (size_t)(col0 + w_r) * 512;

    float4 xa0 = *(const float4*)(xrow + a_kq * 4);
    float4 xa1 = *(const float4*)(xrow + (a_kq + 2) * 4);
    if (x2row) {
        float4 d0 = *(const float4*)(x2row + a_kq * 4);
        float4 d1 = *(const float4*)(x2row + (a_kq + 2) * 4);
        xa0.x -= d0.x; xa0.y -= d0.y; xa0.z -= d0.z; xa0.w -= d0.w;
        xa1.x -= d1.x; xa1.y -= d1.y; xa1.z -= d1.z; xa1.w -= d1.w;
    }
    float4 wa = *(const float4*)(wrow + w_kq * 4);

    for (int k0 = 0; k0 < 512; k0 += 16) {
        int ak0 = a_kq * 4, ak1 = (a_kq + 2) * 4, wk = w_kq * 4;
        As[ak0 + 0][a_r] = xa0.x; As[ak0 + 1][a_r] = xa0.y;
        As[ak0 + 2][a_r] = xa0.z; As[ak0 + 3][a_r] = xa0.w;
        As[ak1 + 0][a_r] = xa1.x; As[ak1 + 1][a_r] = xa1.y;
        As[ak1 + 2][a_r] = xa1.z; As[ak1 + 3][a_r] = xa1.w;
        Bs[wk + 0][w_r] = wa.x; Bs[wk + 1][w_r] = wa.y;
        Bs[wk + 2][w_r] = wa.z; Bs[wk + 3][w_r] = wa.w;
        __syncthreads();

        if (k0 + 16 < 512) {
            int kn = k0 + 16;
            xa0 = *(const float4*)(xrow + kn + a_kq * 4);
            xa1 = *(const float4*)(xrow + kn + (a_kq + 2) * 4);
            if (x2row) {
                float4 d0 = *(const float4*)(x2row + kn + a_kq * 4);
                float4 d1 = *(const float4*)(x2row + kn + (a_kq + 2) * 4);
                xa0.x -= d0.x; xa0.y -= d0.y; xa0.z -= d0.z; xa0.w -= d0.w;
                xa1.x -= d1.x; xa1.y -= d1.y; xa1.z -= d1.z; xa1.w -= d1.w;
            }
            wa = *(const float4*)(wrow + kn + w_kq * 4);
        }

#pragma unroll
        for (int kk = 0; kk < 16; kk++) {
            float4 a0 = *(const float4*)&As[kk][ty * 8];
            float4 a1 = *(const float4*)&As[kk][ty * 8 + 4];
            float4 b4 = *(const float4*)&Bs[kk][tx * 4];
            float a[8] = {a0.x, a0.y, a0.z, a0.w, a1.x, a1.y, a1.z, a1.w};
            float b[4] = {b4.x, b4.y, b4.z, b4.w};
#pragma unroll
            for (int i = 0; i < 8; i++)
#pragma unroll
                for (int j = 0; j < 4; j++) acc[i][j] += a[i] * b[j];
        }
        __syncthreads();
    }

    float4 badd = make_float4(0.f, 0.f, 0.f, 0.f);
    if (bias) {
        const float* bb = bias + (size_t)c * bStride + col0 + tx * 4;
        badd = make_float4(bb[0], bb[1], bb[2], bb[3]);
    }
#pragma unroll
    for (int i = 0; i < 8; i++) {
        int r = row0 + ty * 8 + i;
        float4 o = make_float4(acc[i][0] + badd.x, acc[i][1] + badd.y,
                               acc[i][2] + badd.z, acc[i][3] + badd.w);
        *(float4*)(out + ((size_t)c * N + r) * 512 + col0 + tx * 4) = o;
    }
}

// ---------------------------------------------------------------------------
// Fused scores + softmax, micro-tiled (v2):
//   S[g, t, s] = softmax_s( temp * sum_dc K[dc,t] * V[dc,s] )
//   Block: 256 threads, owns 32 t-rows x full TB s-range.
//   Compute: s-tiles of 128; per-thread 4x4 micro-tile (2x LDS.128 + 16 FFMA
//   per dc). K, V(tile), and the 32xTB score panel staged in dynamic smem.
//   Softmax: warp-per-row shuffle reductions; normalized write, S once.
// ---------------------------------------------------------------------------
template<int TB>
__global__ __launch_bounds__(256) void attn_scores_softmax_t(
    const float* __restrict__ Kb, const float* __restrict__ Vb,
    float* __restrict__ S, const float* __restrict__ temp, int tempBase)
{
    extern __shared__ float sm[];
    float* Ks = sm;                       // 32 x 36 (pad keeps 16B align)
    float* Vs = sm + 32 * 36;             // 32 x 132
    float* Ss = sm + 32 * 36 + 32 * 132;  // 32 x TB

    int g = blockIdx.z;
    int c = g >> 9;               // /512 (B*H)
    int bh = g & 511;
    int b = bh >> 4, h = bh & 15;
    size_t base = (size_t)(c * 32 + b) * TB * 512 + (size_t)h * 32 * TB;
    const float* K = Kb + base;
    const float* V = Vb + base;
    float tscale = temp[tempBase + c * 16 + h];

    int t0 = blockIdx.y * 32;
    int tid = threadIdx.x;
    int tx = tid & 31;            // s col-group (4 cols)
    int ty = tid >> 5;            // t row-group (4 rows); == warp id

    // ---- stage K tile (32 dc x 32 t) ----
    for (int i = tid; i < 1024; i += 256) {
        int dc = i >> 5, tl = i & 31;
        Ks[dc * 36 + tl] = K[dc * TB + t0 + tl];
    }

    // ---- compute scores into Ss, s-tiles of 128 ----
    for (int s0 = 0; s0 < TB; s0 += 128) {
        // stage V tile (32 dc x 128 s), coalesced float4
        for (int i = tid; i < 1024; i += 256) {
            int dc = i >> 5, sc = (i & 31) * 4;
            *(float4*)&Vs[dc * 132 + sc] =
                *(const float4*)&V[dc * TB + s0 + sc];
        }
        __syncthreads();   // Ks (iter 0) + Vs visible

        float acc[4][4];
#pragma unroll
        for (int i = 0; i < 4; i++)
#pragma unroll
            for (int j = 0; j < 4; j++) acc[i][j] = 0.0f;

#pragma unroll
        for (int dc = 0; dc < 32; dc++) {
            float4 kv = *(const float4*)&Ks[dc * 36 + ty * 4];
            float4 vv = *(const float4*)&Vs[dc * 132 + tx * 4];
            float a[4] = {kv.x, kv.y, kv.z, kv.w};
            float v[4] = {vv.x, vv.y, vv.z, vv.w};
#pragma unroll
            for (int i = 0; i < 4; i++)
#pragma unroll
                for (int j = 0; j < 4; j++) acc[i][j] += a[i] * v[j];
        }

#pragma unroll
        for (int i = 0; i < 4; i++) {
            float4 o = make_float4(acc[i][0] * tscale, acc[i][1] * tscale,
                                   acc[i][2] * tscale, acc[i][3] * tscale);
            *(float4*)&Ss[(ty * 4 + i) * TB + s0 + tx * 4] = o;
        }
        __syncthreads();   // Ss done / protect Vs for next tile
    }

    // ---- softmax: warp ty handles rows ty*4 .. ty*4+3 ----
    const int NV = TB / 32;
    int lane = tid & 31;
    float* Sg = S + (size_t)g * TB * TB;
#pragma unroll
    for (int i = 0; i < 4; i++) {
        int r = ty * 4 + i;
        float vals[NV];
        float m = -1e30f;
#pragma unroll
        for (int k = 0; k < NV; k++) {
            vals[k] = Ss[r * TB + k * 32 + lane];
            m = fmaxf(m, vals[k]);
        }
#pragma unroll
        for (int o = 16; o > 0; o >>= 1)
            m = fmaxf(m, __shfl_xor_sync(0xffffffffu, m, o));
        float sum = 0.0f;
#pragma unroll
        for (int k = 0; k < NV; k++) {
            vals[k] = __expf(vals[k] - m);
            sum += vals[k];
        }
#pragma unroll
        for (int o = 16; o > 0; o >>= 1)
            sum += __shfl_xor_sync(0xffffffffu, sum, o);
        float inv = 1.0f / sum;
        float* row = Sg + (size_t)(t0 + r) * TB;
#pragma unroll
        for (int k = 0; k < NV; k++)
            row[k * 32 + lane] = vals[k] * inv;
    }
}

// ---------------------------------------------------------------------------
// Apply, micro-tiled (v2): O[dc, s] = sum_t Q[dc,t] * A[t,s]
//   Block: 256 threads, 32 dc x 128 s tile; t-loop in 32-tiles.
//   Q staged transposed [t][dc] (pitch 36), A staged [t][s] (pitch 132);
//   per-thread 4x4 micro-tile -> 16 FMA per 2 LDS.128.
//   Output written to (B,384,512) layout at
//   idx = b*196608 + c*TB*512 + h*32*TB + dc*TB + s  (+ optional residual)
// ---------------------------------------------------------------------------
template<int TB>
__global__ __launch_bounds__(256) void attn_out_t(
    const float* __restrict__ Qb, const float* __restrict__ S,
    const float* __restrict__ resid, float* __restrict__ out)
{
    __shared__ float Qs[32 * 36];    // [t][dc] transposed
    __shared__ float As[32 * 132];   // [t][s]

    int g = blockIdx.z;
    int c = g >> 9;
    int bh = g & 511;
    int b = bh >> 4, h = bh & 15;
    const float* Q = Qb + (size_t)(c * 32 + b) * TB * 512 + (size_t)h * 32 * TB;
    const float* A = S + (size_t)g * TB * TB;
    int s0 = blockIdx.x * 128;
    int tid = threadIdx.x;
    int tx = tid & 31;            // s col-group (4 cols)
    int ty = tid >> 5;            // dc row-group (4 rows)

    float acc[4][4];
#pragma unroll
    for (int i = 0; i < 4; i++)
#pragma unroll
        for (int j = 0; j < 4; j++) acc[i][j] = 0.0f;

    for (int t0 = 0; t0 < TB; t0 += 32) {
        __syncthreads();          // protect prev iteration's tile reads
        // stage Q (32 dc x 32 t), transposed to [t][dc]; coalesced global read
        for (int i = tid; i < 1024; i += 256) {
            int dc = i >> 5, tl = i & 31;
            Qs[tl * 36 + dc] = Q[dc * TB + t0 + tl];
        }
        // stage A (32 t x 128 s), coalesced float4
        for (int i = tid; i < 1024; i += 256) {
            int rr = i >> 5, sc = (i & 31) * 4;
            *(float4*)&As[rr * 132 + sc] =
                *(const float4*)&A[(size_t)(t0 + rr) * TB + s0 + sc];
        }
        __syncthreads();

#pragma unroll
        for (int tt = 0; tt < 32; tt++) {
            float4 qv = *(const float4*)&Qs[tt * 36 + ty * 4];
            float4 av = *(const float4*)&As[tt * 132 + tx * 4];
            float q[4] = {qv.x, qv.y, qv.z, qv.w};
            float a[4] = {av.x, av.y, av.z, av.w};
#pragma unroll
            for (int i = 0; i < 4; i++)
#pragma unroll
                for (int j = 0; j < 4; j++) acc[i][j] += q[i] * a[j];
        }
    }

    size_t base = (size_t)b * 196608 + (size_t)c * TB * 512 + (size_t)h * 32 * TB;
#pragma unroll
    for (int i = 0; i < 4; i++) {
        int dc = ty * 4 + i;
        size_t idx = base + (size_t)dc * TB + s0 + tx * 4;
        float4 v = make_float4(acc[i][0], acc[i][1], acc[i][2], acc[i][3]);
        if (resid) {
            float4 rv = *(const float4*)(resid + idx);
            v.x += rv.x; v.y += rv.y; v.z += rv.z; v.w += rv.w;
        }
        *(float4*)(out + idx) = v;
    }
}

// ---------------------------------------------------------------------------
// LayerNorm over last dim (512), one block (128 threads x float4) per row
// ---------------------------------------------------------------------------
__global__ __launch_bounds__(128) void layernorm_rows(
    const float* __restrict__ X, float* __restrict__ Y,
    const float* __restrict__ gam, const float* __restrict__ bet)
{
    size_t r = blockIdx.x;
    int tid = threadIdx.x;
    float4 v = ((const float4*)(X + r * 512))[tid];
    __shared__ float red[128];

    red[tid] = v.x + v.y + v.z + v.w; __syncthreads();
    for (int o = 64; o > 0; o >>= 1) {
        if (tid < o) red[tid] += red[tid + o];
        __syncthreads();
    }
    float mu = red[0] * (1.0f / 512.0f); __syncthreads();

    float4 d = make_float4(v.x - mu, v.y - mu, v.z - mu, v.w - mu);
    red[tid] = d.x * d.x + d.y * d.y + d.z * d.z + d.w * d.w; __syncthreads();
    for (int o = 64; o > 0; o >>= 1) {
        if (tid < o) red[tid] += red[tid + o];
        __syncthreads();
    }
    float inv = rsqrtf(red[0] * (1.0f / 512.0f) + 1e-5f);

    int cidx = tid * 4;
    float4 o;
    o.x = d.x * inv * gam[cidx + 0] + bet[cidx + 0];
    o.y = d.y * inv * gam[cidx + 1] + bet[cidx + 1];
    o.z = d.z * inv * gam[cidx + 2] + bet[cidx + 2];
    o.w = d.w * inv * gam[cidx + 3] + bet[cidx + 3];
    ((float4*)(Y + r * 512))[tid] = o;
}

// out = t2 + (t1 - t2) * sigmoid(g)   [== softmax fusion gate, bias cancels]
__global__ __launch_bounds__(256) void fuse_out(
    const float* __restrict__ t1, const float* __restrict__ t2,
    const float* __restrict__ gg, float* __restrict__ out, int n4)
{
    int i = blockIdx.x * 256 + threadIdx.x;
    if (i >= n4) return;
    float4 a = ((const float4*)t1)[i];
    float4 b = ((const float4*)t2)[i];
    float4 g = ((const float4*)gg)[i];
    float4 o;
    o.x = b.x + (a.x - b.x) * (1.0f / (1.0f + __expf(-g.x)));
    o.y = b.y + (a.y - b.y) * (1.0f / (1.0f + __expf(-g.y)));
    o.z = b.z + (a.z - b.z) * (1.0f / (1.0f + __expf(-g.z)));
    o.w = b.w + (a.w - b.w) * (1.0f / (1.0f + __expf(-g.w)));
    ((float4*)out)[i] = o;
}

// ---------------------------------------------------------------------------
extern "C" void kernel_launch(void* const* d_in, const int* in_sizes, int n_in,
                              void* d_out, int out_size)
{
    const float* x     = (const float*)d_in[0];
    const float* qw    = (const float*)d_in[1];
    const float* qb    = (const float*)d_in[2];
    const float* kw    = (const float*)d_in[3];
    const float* kb    = (const float*)d_in[4];
    const float* vw    = (const float*)d_in[5];
    const float* vb    = (const float*)d_in[6];
    const float* temp  = (const float*)d_in[7];
    const float* ln_g  = (const float*)d_in[8];
    const float* ln_b  = (const float*)d_in[9];
    const float* fus_w = (const float*)d_in[10];
    const float* fus_b = (const float*)d_in[11];
    (void)fus_b; (void)in_sizes; (void)n_in; (void)out_size;
    float* out = (float*)d_out;

    float *bq, *bk, *bv, *bxr, *bt1, *bt2, *bln, *bS;
    cudaGetSymbolAddress((void**)&bq,  g_q);
    cudaGetSymbolAddress((void**)&bk,  g_k);
    cudaGetSymbolAddress((void**)&bv,  g_v);
    cudaGetSymbolAddress((void**)&bxr, g_xr);
    cudaGetSymbolAddress((void**)&bt1, g_t1);
    cudaGetSymbolAddress((void**)&bt2, g_t2);
    cudaGetSymbolAddress((void**)&bln, g_ln);
    cudaGetSymbolAddress((void**)&bS,  g_S);

    const int WS = 512 * 512;  // per-block weight stride
    const int BS = 512;        // per-block bias stride
    const int n4 = 6291456 / 4;

    // smem sizes for the templated scores kernels (set every call; idempotent,
    // host-side only, capture-safe — no static guards per harness rules)
    const int SMEM_F = (32 * 36 + 32 * 132 + 32 * 384) * 4;  // 70656 B
    const int SMEM_C = (32 * 36 + 32 * 132 + 32 * 128) * 4;  // 37888 B
    cudaFuncSetAttribute(attn_scores_softmax_t<384>,
                         cudaFuncAttributeMaxDynamicSharedMemorySize, SMEM_F);
    cudaFuncSetAttribute(attn_scores_softmax_t<128>,
                         cudaFuncAttributeMaxDynamicSharedMemorySize, SMEM_C);

    // ---- Block 0 (full T=384) -> x_ ----
    dim3 gF(8, 96, 1);         // 64-col x 128-row tiles over 12288 rows
    gemm512<<<gF, 256>>>(x, nullptr, qw + 0 * WS, qb + 0 * BS, bq, 384, WS, BS);
    gemm512<<<gF, 256>>>(x, nullptr, kw + 0 * WS, kb + 0 * BS, bk, 384, WS, BS);
    gemm512<<<gF, 256>>>(x, nullptr, vw + 0 * WS, vb + 0 * BS, bv, 384, WS, BS);
    attn_scores_softmax_t<384><<<dim3(1, 12, 512), 256, SMEM_F>>>(bk, bv, bS, temp, 0);
    attn_out_t<384><<<dim3(3, 1, 512), 256>>>(bq, bS, nullptr, bxr);

    // ---- Chunk blocks 1..3 (T=128 each), batched via gridDim.z -> tmp1 ----
    dim3 gC(8, 32, 3);         // 4096 rows per chunk-block
    gemm512<<<gC, 256>>>(x, nullptr, qw + 1 * WS, qb + 1 * BS, bq, 128, WS, BS);
    gemm512<<<gC, 256>>>(x, nullptr, kw + 1 * WS, kb + 1 * BS, bk, 128, WS, BS);
    gemm512<<<gC, 256>>>(x, nullptr, vw + 1 * WS, vb + 1 * BS, bv, 128, WS, BS);
    attn_scores_softmax_t<128><<<dim3(1, 4, 1536), 256, SMEM_C>>>(bk, bv, bS, temp, 16);
    attn_out_t<128><<<dim3(1, 1, 1536), 256>>>(bq, bS, bxr, bt1);

    // ---- LayerNorm(tmp1) ----
    layernorm_rows<<<12288, 128>>>(bt1, bln, ln_g, ln_b);

    // ---- Block 4 (full T=384) on ln -> tmp2 ----
    gemm512<<<gF, 256>>>(bln, nullptr, qw + 4 * WS, qb + 4 * BS, bq, 384, WS, BS);
    gemm512<<<gF, 256>>>(bln, nullptr, kw + 4 * WS, kb + 4 * BS, bk, 384, WS, BS);
    gemm512<<<gF, 256>>>(bln, nullptr, vw + 4 * WS, vb + 4 * BS, bv, 384, WS, BS);
    attn_scores_softmax_t<384><<<dim3(1, 12, 512), 256, SMEM_F>>>(bk, bv, bS, temp, 64);
    attn_out_t<384><<<dim3(3, 1, 512), 256>>>(bq, bS, bxr, bt2);

    // ---- Fusion gate: g = (tmp1 - tmp2) @ fus_w^T (bias cancels in softmax;
    //      diff fused into the GEMM's A-tile load) ----
    gemm512<<<gF, 256>>>(bt1, bt2, fus_w, nullptr, bk, 384, 0, 0);
    fuse_out<<<(n4 + 255) / 256, 256>>>(bt1, bt2, bk, out, n4);
}